// round 1
// baseline (speedup 1.0000x reference)
#include <cuda_runtime.h>

#define NN   110
#define BB   2048
#define NH1  5
#define F1   24
#define HF1  120   // NH1*F1
#define NH2  3
#define F2   3
#define ALPHA 0.2f
#define NTHREADS 512

#define XS_STRIDE 113
#define XS_ROWS   112

// shared-memory layout (float offsets)
#define OFF_XS   0
#define SZ_XS    (XS_ROWS*XS_STRIDE)          // 12656 (Xm, later P buffer)
#define OFF_W1H  (OFF_XS + SZ_XS)             // 12656 (W1t, later h1) - 16B aligned
#define SZ_W1H   (NN*HF1)                     // 13200
#define OFF_FE   (OFF_W1H + SZ_W1H)           // 25856 (feats) - 16B aligned
#define SZ_FE    (NN*HF1)
#define OFF_ES1  (OFF_FE + SZ_FE)             // 39056
#define OFF_EN1  (OFF_ES1 + NH1*NN)
#define OFF_ZS   (OFF_EN1 + NH1*NN)
#define OFF_AM   (OFF_ZS + NN)                // 440 uint32 words
#define OFF_F2S  (OFF_AM + NN*4)
#define OFF_HO2  (OFF_F2S + NN*9)
#define OFF_ES2  (OFF_HO2 + NN*9)
#define OFF_EN2  (OFF_ES2 + NH2*NN)
#define OFF_TS   (OFF_EN2 + NH2*NN)
#define OFF_YS   (OFF_TS + NN)
#define SMEM_FLOATS (OFF_YS + NN + 2)
#define SMEM_BYTES  (SMEM_FLOATS*4)

__device__ float g_sigM[NN*NN];
__device__ float g_W1t[NN*HF1];   // [k][h*F1+f]

__global__ void prep_kernel(const float* __restrict__ M, const float* __restrict__ W1) {
    int i = blockIdx.x*blockDim.x + threadIdx.x;
    if (i < NN*NN) g_sigM[i] = 1.f/(1.f + expf(-M[i]));
    if (i < NN*HF1) {
        int k = i / HF1, hf = i - k*HF1;
        int h = hf / F1, f = hf - h*F1;
        g_W1t[i] = W1[(h*NN + k)*F1 + f];
    }
}

__device__ __forceinline__ float wred_max(float v) {
    #pragma unroll
    for (int o = 16; o > 0; o >>= 1) v = fmaxf(v, __shfl_xor_sync(0xffffffffu, v, o));
    return v;
}
__device__ __forceinline__ float wred_sum(float v) {
    #pragma unroll
    for (int o = 16; o > 0; o >>= 1) v += __shfl_xor_sync(0xffffffffu, v, o);
    return v;
}

__global__ __launch_bounds__(NTHREADS, 1)
void gat_kernel(const float* __restrict__ X, const float* __restrict__ A,
                const float* __restrict__ as1, const float* __restrict__ an1,
                const float* __restrict__ b1,
                const float* __restrict__ W2,  const float* __restrict__ as2,
                const float* __restrict__ an2, const float* __restrict__ b2,
                const float* __restrict__ fc1, const float* __restrict__ fc2,
                float* __restrict__ out)
{
    extern __shared__ float sm[];
    float*    Xs    = sm + OFF_XS;
    float*    W1h   = sm + OFF_W1H;   // reused as h1 output
    float*    feats = sm + OFF_FE;
    float*    es1   = sm + OFF_ES1;
    float*    en1   = sm + OFF_EN1;
    float*    Zs    = sm + OFF_ZS;
    unsigned* Amask = (unsigned*)(sm + OFF_AM);
    float*    f2s   = sm + OFF_F2S;
    float*    ho2   = sm + OFF_HO2;
    float*    es2   = sm + OFF_ES2;
    float*    en2   = sm + OFF_EN2;
    float*    ts    = sm + OFF_TS;
    float*    ys    = sm + OFF_YS;

    const int b = blockIdx.x;
    const int t = threadIdx.x;
    const int w = t >> 5, lane = t & 31;
    const float* Xb = X + (size_t)b*NN*NN;
    const float* Ab = A + (size_t)b*NN*NN;

    // ---- stage 1: load Xm, W1t, adjacency bitmask --------------------------
    for (int i = t; i < NN*NN; i += NTHREADS) {
        int n = i / NN, k = i - n*NN;
        Xs[n*XS_STRIDE + k] = Xb[i] * g_sigM[i];
    }
    for (int i = t; i < 2*XS_STRIDE; i += NTHREADS) Xs[NN*XS_STRIDE + i] = 0.f;  // pad rows 110,111
    for (int i = t; i < NN*HF1; i += NTHREADS) W1h[i] = g_W1t[i];
    for (int task = w; task < NN*4; task += 16) {
        int n = task >> 2, q = task & 3;
        int j = q*32 + lane;
        bool pred = (j < NN) && (Ab[n*NN + j] > 0.f);
        unsigned word = __ballot_sync(0xffffffffu, pred);
        if (lane == 0) Amask[task] = word;
    }
    __syncthreads();

    // ---- GEMM1: feats[n][hf] = sum_k Xm[n][k] * W1t[k][hf] ----------------
    if (t < 480) {
        int rt = t / 30, ct = t - (t/30)*30;   // rt: 16 row tiles of 7, ct: 30 col tiles of 4
        int n0 = rt * 7;
        float acc[7][4];
        #pragma unroll
        for (int r = 0; r < 7; r++) { acc[r][0]=acc[r][1]=acc[r][2]=acc[r][3]=0.f; }
        const float4* Wv = (const float4*)W1h;
        #pragma unroll 2
        for (int k = 0; k < NN; k++) {
            float4 wv = Wv[k*30 + ct];
            #pragma unroll
            for (int r = 0; r < 7; r++) {
                float xv = Xs[(n0+r)*XS_STRIDE + k];
                acc[r][0] = fmaf(xv, wv.x, acc[r][0]);
                acc[r][1] = fmaf(xv, wv.y, acc[r][1]);
                acc[r][2] = fmaf(xv, wv.z, acc[r][2]);
                acc[r][3] = fmaf(xv, wv.w, acc[r][3]);
            }
        }
        #pragma unroll
        for (int r = 0; r < 7; r++) {
            int n = n0 + r;
            if (n < NN) {
                float* fp = feats + n*HF1 + ct*4;
                fp[0]=acc[r][0]; fp[1]=acc[r][1]; fp[2]=acc[r][2]; fp[3]=acc[r][3];
            }
        }
    }
    __syncthreads();

    // ---- attention logits source/neighbor terms ---------------------------
    for (int i = t; i < NH1*NN; i += NTHREADS) {
        int h = i / NN, n = i - h*NN;
        const float* fr = feats + n*HF1 + h*F1;
        float a = 0.f, c = 0.f;
        #pragma unroll
        for (int f = 0; f < F1; f++) {
            float v = fr[f];
            a = fmaf(v, __ldg(as1 + h*F1 + f), a);
            c = fmaf(v, __ldg(an1 + h*F1 + f), c);
        }
        es1[i] = a; en1[i] = c;
    }
    __syncthreads();

    float* Ps = Xs;    // Xm no longer needed
    float* h1 = W1h;   // W1t no longer needed

    // ---- per-head masked softmax + aggregate ------------------------------
    for (int h = 0; h < NH1; h++) {
        // softmax row-wise (unnormalized P + row sums)
        for (int row = w; row < NN; row += 16) {
            float esr = es1[h*NN + row];
            float ev[4]; unsigned bits[4];
            float m = -1e30f;
            #pragma unroll
            for (int q = 0; q < 4; q++) {
                int j = q*32 + lane;
                unsigned bit = 0; float e = -1e30f;
                if (j < NN) {
                    bit = (Amask[row*4 + q] >> lane) & 1u;
                    e = esr + en1[h*NN + j];
                    e = fmaxf(e, ALPHA*e);         // leaky_relu
                    if (bit) m = fmaxf(m, e);
                }
                ev[q] = e; bits[q] = bit;
            }
            m = wred_max(m);
            float s = 0.f;
            #pragma unroll
            for (int q = 0; q < 4; q++) {
                int j = q*32 + lane;
                if (j < NN) {
                    float p = bits[q] ? __expf(ev[q] - m) : 0.f;
                    Ps[row*XS_STRIDE + j] = p;
                    s += p;
                }
            }
            s = wred_sum(s);
            if (lane == 0) Zs[row] = s;
        }
        __syncthreads();

        // aggregate: h1[n][h*F1+f] = lrelu( (sum_j P[n][j]*feats[j][h*F1+f]) / Z[n] + b1[f] )
        if (t < 168) {
            int rt = t / 6, ct = t - (t/6)*6;   // rt: 28 row tiles of 4, ct: 6 f-tiles of 4
            int n0 = rt * 4;
            float acc[4][4];
            #pragma unroll
            for (int r = 0; r < 4; r++) { acc[r][0]=acc[r][1]=acc[r][2]=acc[r][3]=0.f; }
            const float4* Fv = (const float4*)feats;
            #pragma unroll 2
            for (int k = 0; k < NN; k++) {
                float4 fv = Fv[k*30 + h*6 + ct];
                #pragma unroll
                for (int r = 0; r < 4; r++) {
                    float p = Ps[(n0+r)*XS_STRIDE + k];
                    acc[r][0] = fmaf(p, fv.x, acc[r][0]);
                    acc[r][1] = fmaf(p, fv.y, acc[r][1]);
                    acc[r][2] = fmaf(p, fv.z, acc[r][2]);
                    acc[r][3] = fmaf(p, fv.w, acc[r][3]);
                }
            }
            #pragma unroll
            for (int r = 0; r < 4; r++) {
                int n = n0 + r;
                if (n < NN) {
                    float invZ = 1.f / Zs[n];
                    float* hp = h1 + n*HF1 + h*F1 + ct*4;
                    #pragma unroll
                    for (int c = 0; c < 4; c++) {
                        float v = fmaf(acc[r][c], invZ, __ldg(b1 + ct*4 + c));
                        hp[c] = fmaxf(v, ALPHA*v);
                    }
                }
            }
        }
        __syncthreads();
    }

    // ---- layer 2: projections ---------------------------------------------
    for (int i = t; i < NN*9; i += NTHREADS) {
        int n = i / 9, hf = i - n*9;
        int h = hf / 3, f = hf - h*3;
        const float* hr = h1 + n*HF1;
        const float* wp = W2 + (h*HF1)*F2 + f;
        float a = 0.f;
        #pragma unroll 4
        for (int k2 = 0; k2 < HF1; k2++) a = fmaf(hr[k2], __ldg(wp + k2*F2), a);
        f2s[i] = a;
    }
    __syncthreads();
    for (int i = t; i < NH2*NN; i += NTHREADS) {
        int h = i / NN, n = i - h*NN;
        const float* fr = f2s + n*9 + h*3;
        float a = fr[0]*__ldg(as2+h*3) + fr[1]*__ldg(as2+h*3+1) + fr[2]*__ldg(as2+h*3+2);
        float c = fr[0]*__ldg(an2+h*3) + fr[1]*__ldg(an2+h*3+1) + fr[2]*__ldg(an2+h*3+2);
        es2[i] = a; en2[i] = c;
    }
    __syncthreads();

    // ---- layer-2 softmax + aggregate (warp per (h,row)) -------------------
    for (int task = w; task < NH2*NN; task += 16) {
        int h = task / NN, n = task - h*NN;
        float esr = es2[task];
        float ev[4]; unsigned bits[4];
        float m = -1e30f;
        #pragma unroll
        for (int q = 0; q < 4; q++) {
            int j = q*32 + lane;
            unsigned bit = 0; float e = -1e30f;
            if (j < NN) {
                bit = (Amask[n*4 + q] >> lane) & 1u;
                e = esr + en2[h*NN + j];
                e = fmaxf(e, ALPHA*e);
                if (bit) m = fmaxf(m, e);
            }
            ev[q] = e; bits[q] = bit;
        }
        m = wred_max(m);
        float s0 = 0.f, s1 = 0.f, s2 = 0.f, s3 = 0.f;
        #pragma unroll
        for (int q = 0; q < 4; q++) {
            int j = q*32 + lane;
            if (j < NN && bits[q]) {
                float p = __expf(ev[q] - m);
                const float* fj = f2s + j*9 + h*3;
                s0 += p;
                s1 = fmaf(p, fj[0], s1);
                s2 = fmaf(p, fj[1], s2);
                s3 = fmaf(p, fj[2], s3);
            }
        }
        s0 = wred_sum(s0); s1 = wred_sum(s1); s2 = wred_sum(s2); s3 = wred_sum(s3);
        if (lane == 0) {
            float inv = 1.f / s0;
            ho2[n*9 + h*3 + 0] = s1*inv;
            ho2[n*9 + h*3 + 1] = s2*inv;
            ho2[n*9 + h*3 + 2] = s3*inv;
        }
    }
    __syncthreads();

    // ---- head mean + lrelu + fc1 + sigmoid --------------------------------
    if (t < NN) {
        int n = t;
        float s = 0.f;
        #pragma unroll
        for (int f = 0; f < 3; f++) {
            float v = (ho2[n*9 + f] + ho2[n*9 + 3 + f] + ho2[n*9 + 6 + f]) * (1.f/3.f)
                      + __ldg(b2 + f);
            v = fmaxf(v, ALPHA*v);
            s = fmaf(v, __ldg(fc1 + f), s);
        }
        ts[n] = 1.f/(1.f + __expf(-s));
    }
    __syncthreads();

    // ---- y = t @ fc2 -------------------------------------------------------
    if (t < NN) {
        int j = t;
        float a = 0.f;
        #pragma unroll 2
        for (int n = 0; n < NN; n++) a = fmaf(ts[n], __ldg(fc2 + n*NN + j), a);
        ys[j] = a;
    }
    __syncthreads();

    // ---- final: out[b] = sum_j t[j]*softmax(y)[j] --------------------------
    if (t < 32) {
        float yv[4];
        float m = -1e30f;
        #pragma unroll
        for (int q = 0; q < 4; q++) {
            int j = q*32 + t;
            yv[q] = (j < NN) ? ys[j] : -1e30f;
            m = fmaxf(m, yv[q]);
        }
        m = wred_max(m);
        float S = 0.f, T = 0.f;
        #pragma unroll
        for (int q = 0; q < 4; q++) {
            int j = q*32 + t;
            if (j < NN) {
                float p = __expf(yv[q] - m);
                S += p;
                T = fmaf(ts[j], p, T);
            }
        }
        S = wred_sum(S); T = wred_sum(T);
        if (t == 0) out[b] = T / S;
    }
}

extern "C" void kernel_launch(void* const* d_in, const int* in_sizes, int n_in,
                              void* d_out, int out_size) {
    (void)in_sizes; (void)n_in; (void)out_size;
    const float* X   = (const float*)d_in[0];
    const float* A   = (const float*)d_in[1];
    const float* M   = (const float*)d_in[2];
    const float* W1  = (const float*)d_in[3];
    const float* as1 = (const float*)d_in[4];
    const float* an1 = (const float*)d_in[5];
    const float* b1  = (const float*)d_in[6];
    const float* W2  = (const float*)d_in[7];
    const float* as2 = (const float*)d_in[8];
    const float* an2 = (const float*)d_in[9];
    const float* b2  = (const float*)d_in[10];
    const float* fc1 = (const float*)d_in[11];
    const float* fc2 = (const float*)d_in[12];

    cudaFuncSetAttribute(gat_kernel, cudaFuncAttributeMaxDynamicSharedMemorySize, SMEM_BYTES);

    prep_kernel<<<(NN*HF1 + 255)/256, 256>>>(M, W1);
    gat_kernel<<<BB, NTHREADS, SMEM_BYTES>>>(X, A, as1, an1, b1,
                                             W2, as2, an2, b2, fc1, fc2,
                                             (float*)d_out);
}

// round 3
// speedup vs baseline: 1.4617x; 1.4617x over previous
#include <cuda_runtime.h>
#include <cuda_fp16.h>

#define NN   110
#define BB   2048
#define NH1  5
#define F1   24
#define HF1  120   // NH1*F1
#define NH2  3
#define F2   3
#define ALPHA 0.2f
#define NT   512

#define XS_STRIDE 113
#define XS_ROWS   112

// ---- shared memory layout (float offsets) ----
#define OFF_XS   0
#define SZ_XS    (XS_ROWS*XS_STRIDE)          // 12656 : Xm, then P, then layer-2 scratch
#define OFF_FEH  (OFF_XS + SZ_XS)             // feats fp16: NN*HF1 halves = 6600 floats
#define SZ_FEH   (NN*HF1/2)
#define OFF_H1H  (OFF_FEH + SZ_FEH)           // h1 fp16: 6600 floats
#define SZ_H1H   (NN*HF1/2)
#define OFF_ES1  (OFF_H1H + SZ_H1H)           // 550
#define OFF_EN1  (OFF_ES1 + NH1*NN)           // 550
#define OFF_ZS   (OFF_EN1 + NH1*NN)           // 110
#define OFF_AM   (OFF_ZS + NN)                // 440 uint32 words
#define SMEM_FLOATS (OFF_AM + NN*4)
#define SMEM_BYTES  (SMEM_FLOATS*4)           // 110024 B -> 2 CTAs/SM

// layer-2 scratch aliased into the (dead) Xs/P region:
#define L2_F2S  0        // 990
#define L2_HO2  990      // 990
#define L2_ES2  1980     // 330
#define L2_EN2  2310     // 330
#define L2_TS   2640     // 110
#define L2_YS   2752     // 112

__device__ float g_sigM[NN*NN];
__device__ float g_W1t[NN*HF1];   // [k][h*F1+f]

__global__ void prep_kernel(const float* __restrict__ M, const float* __restrict__ W1) {
    int i = blockIdx.x*blockDim.x + threadIdx.x;
    if (i < NN*NN) g_sigM[i] = 1.f/(1.f + expf(-M[i]));
    if (i < NN*HF1) {
        int k = i / HF1, hf = i - k*HF1;
        int h = hf / F1, f = hf - h*F1;
        g_W1t[i] = W1[(h*NN + k)*F1 + f];
    }
}

__device__ __forceinline__ float wred_max(float v) {
    #pragma unroll
    for (int o = 16; o > 0; o >>= 1) v = fmaxf(v, __shfl_xor_sync(0xffffffffu, v, o));
    return v;
}
__device__ __forceinline__ float wred_sum(float v) {
    #pragma unroll
    for (int o = 16; o > 0; o >>= 1) v += __shfl_xor_sync(0xffffffffu, v, o);
    return v;
}

__global__ __launch_bounds__(NT, 2)
void gat_kernel(const float* __restrict__ X, const float* __restrict__ A,
                const float* __restrict__ as1, const float* __restrict__ an1,
                const float* __restrict__ b1,
                const float* __restrict__ W2,  const float* __restrict__ as2,
                const float* __restrict__ an2, const float* __restrict__ b2,
                const float* __restrict__ fc1, const float* __restrict__ fc2,
                float* __restrict__ out)
{
    extern __shared__ float sm[];
    float*    Xs     = sm + OFF_XS;            // Xm -> P -> layer2 scratch
    __half*   featsH = (__half*)(sm + OFF_FEH);
    __half*   h1H    = (__half*)(sm + OFF_H1H);
    float*    es1    = sm + OFF_ES1;
    float*    en1    = sm + OFF_EN1;
    float*    Zs     = sm + OFF_ZS;
    unsigned* Amask  = (unsigned*)(sm + OFF_AM);

    const int b = blockIdx.x;
    const int t = threadIdx.x;
    const int w = t >> 5, lane = t & 31;
    const float* Xb = X + (size_t)b*NN*NN;
    const float* Ab = A + (size_t)b*NN*NN;

    // ---- stage 1: Xm into smem, adjacency bitmask --------------------------
    for (int i = t; i < NN*NN; i += NT) {
        int n = i / NN, k = i - n*NN;
        Xs[n*XS_STRIDE + k] = Xb[i] * g_sigM[i];
    }
    for (int i = t; i < 2*XS_STRIDE; i += NT) Xs[NN*XS_STRIDE + i] = 0.f;  // pad rows 110,111
    for (int task = w; task < NN*4; task += 16) {
        int n = task >> 2, q = task & 3;
        int j = q*32 + lane;
        bool pred = (j < NN) && (Ab[n*NN + j] > 0.f);
        unsigned word = __ballot_sync(0xffffffffu, pred);
        if (lane == 0) Amask[task] = word;
    }
    __syncthreads();

    // ---- GEMM1: feats = Xm @ W1t, fused exact-fp32 es/en epilogue ----------
    // warp w owns rows n0=w*7..n0+6; lanes 0..29 own 4-col (float4) tiles.
    {
        const unsigned GM = 0x3fffffffu;
        if (lane < 30) {
            const int ct = lane;
            const int n0 = w * 7;
            float acc[7][4];
            #pragma unroll
            for (int r = 0; r < 7; r++) { acc[r][0]=acc[r][1]=acc[r][2]=acc[r][3]=0.f; }
            const float4* Wg = (const float4*)g_W1t;
            #pragma unroll 2
            for (int k = 0; k < NN; k++) {
                float4 wv = __ldg(Wg + k*30 + ct);
                #pragma unroll
                for (int r = 0; r < 7; r++) {
                    float xv = Xs[(n0+r)*XS_STRIDE + k];    // broadcast within warp
                    acc[r][0] = fmaf(xv, wv.x, acc[r][0]);
                    acc[r][1] = fmaf(xv, wv.y, acc[r][1]);
                    acc[r][2] = fmaf(xv, wv.z, acc[r][2]);
                    acc[r][3] = fmaf(xv, wv.w, acc[r][3]);
                }
            }
            const int h  = ct / 6;
            const int f0 = (ct - h*6) * 4;
            float a0 = __ldg(as1 + h*F1 + f0),     a1 = __ldg(as1 + h*F1 + f0 + 1);
            float a2 = __ldg(as1 + h*F1 + f0 + 2), a3 = __ldg(as1 + h*F1 + f0 + 3);
            float c0 = __ldg(an1 + h*F1 + f0),     c1 = __ldg(an1 + h*F1 + f0 + 1);
            float c2 = __ldg(an1 + h*F1 + f0 + 2), c3 = __ldg(an1 + h*F1 + f0 + 3);
            const int base = h*6;
            #pragma unroll
            for (int r = 0; r < 7; r++) {
                int n = n0 + r;
                float pes = 0.f, pen = 0.f;
                if (n < NN) {
                    __half2* fp = (__half2*)(featsH + n*HF1 + ct*4);
                    fp[0] = __floats2half2_rn(acc[r][0], acc[r][1]);
                    fp[1] = __floats2half2_rn(acc[r][2], acc[r][3]);
                    pes = acc[r][0]*a0 + acc[r][1]*a1 + acc[r][2]*a2 + acc[r][3]*a3;
                    pen = acc[r][0]*c0 + acc[r][1]*c1 + acc[r][2]*c2 + acc[r][3]*c3;
                }
                float te = 0.f, tn = 0.f;
                #pragma unroll
                for (int i = 0; i < 6; i++) {
                    te += __shfl_sync(GM, pes, base + i);
                    tn += __shfl_sync(GM, pen, base + i);
                }
                if (ct == base && n < NN) { es1[h*NN + n] = te; en1[h*NN + n] = tn; }
            }
        }
    }
    __syncthreads();

    float* Ps = Xs;    // Xm no longer needed

    // ---- per-head masked softmax + aggregate ------------------------------
    for (int h = 0; h < NH1; h++) {
        // softmax rows (unnormalized P + row sums)
        for (int row = w; row < NN; row += 16) {
            float esr = es1[h*NN + row];
            float ev[4]; unsigned bits[4];
            float m = -1e30f;
            #pragma unroll
            for (int q = 0; q < 4; q++) {
                int j = q*32 + lane;
                unsigned bit = 0; float e = -1e30f;
                if (j < NN) {
                    bit = (Amask[row*4 + q] >> lane) & 1u;
                    e = esr + en1[h*NN + j];
                    e = fmaxf(e, ALPHA*e);
                    if (bit) m = fmaxf(m, e);
                }
                ev[q] = e; bits[q] = bit;
            }
            m = wred_max(m);
            float s = 0.f;
            #pragma unroll
            for (int q = 0; q < 4; q++) {
                int j = q*32 + lane;
                if (j < NN) {
                    float p = bits[q] ? __expf(ev[q] - m) : 0.f;
                    Ps[row*XS_STRIDE + j] = p;
                    s += p;
                }
            }
            s = wred_sum(s);
            if (lane == 0) Zs[row] = s;
        }
        __syncthreads();

        // aggregate: h1[n][h*24+f] = lrelu( (P[n]·feats[:, h*24+f]) / Z[n] + b1[f] )
        if (t < 330) {
            int rt = t / 6, ct = t - (t/6)*6;   // 55 row tiles of 2, 6 f-tiles of 4
            int n0 = rt * 2;
            float acc[2][4];
            #pragma unroll
            for (int r = 0; r < 2; r++) { acc[r][0]=acc[r][1]=acc[r][2]=acc[r][3]=0.f; }
            const uint2* Fv = (const uint2*)featsH;   // 4 halves per load
            #pragma unroll 2
            for (int k = 0; k < NN; k++) {
                uint2 fv = Fv[k*30 + h*6 + ct];
                float2 f01 = __half22float2(*reinterpret_cast<__half2*>(&fv.x));
                float2 f23 = __half22float2(*reinterpret_cast<__half2*>(&fv.y));
                #pragma unroll
                for (int r = 0; r < 2; r++) {
                    float p = Ps[(n0+r)*XS_STRIDE + k];
                    acc[r][0] = fmaf(p, f01.x, acc[r][0]);
                    acc[r][1] = fmaf(p, f01.y, acc[r][1]);
                    acc[r][2] = fmaf(p, f23.x, acc[r][2]);
                    acc[r][3] = fmaf(p, f23.y, acc[r][3]);
                }
            }
            #pragma unroll
            for (int r = 0; r < 2; r++) {
                int n = n0 + r;
                float invZ = 1.f / Zs[n];
                float v0 = fmaf(acc[r][0], invZ, __ldg(b1 + ct*4 + 0));
                float v1 = fmaf(acc[r][1], invZ, __ldg(b1 + ct*4 + 1));
                float v2 = fmaf(acc[r][2], invZ, __ldg(b1 + ct*4 + 2));
                float v3 = fmaf(acc[r][3], invZ, __ldg(b1 + ct*4 + 3));
                v0 = fmaxf(v0, ALPHA*v0); v1 = fmaxf(v1, ALPHA*v1);
                v2 = fmaxf(v2, ALPHA*v2); v3 = fmaxf(v3, ALPHA*v3);
                __half2* hp = (__half2*)(h1H + n*HF1 + h*F1 + ct*4);
                hp[0] = __floats2half2_rn(v0, v1);
                hp[1] = __floats2half2_rn(v2, v3);
            }
        }
        __syncthreads();
    }

    // layer-2 scratch aliases the P region (dead now)
    float* f2s = Xs + L2_F2S;
    float* ho2 = Xs + L2_HO2;
    float* es2 = Xs + L2_ES2;
    float* en2 = Xs + L2_EN2;
    float* ts  = Xs + L2_TS;
    float* ys  = Xs + L2_YS;

    // ---- layer 2: projections f2s[n][h*3+f] = h1[n]·W2[h][:,f] -------------
    for (int i = t; i < NN*9; i += NT) {
        int n = i / 9, hf = i - n*9;
        int h = hf / 3, f = hf - h*3;
        const __half* hr = h1H + n*HF1;
        const float* wp = W2 + (h*HF1)*F2 + f;
        float a = 0.f;
        #pragma unroll 4
        for (int k2 = 0; k2 < HF1; k2 += 2) {
            float2 fv = __half22float2(*(const __half2*)(hr + k2));
            a = fmaf(fv.x, __ldg(wp + k2*F2), a);
            a = fmaf(fv.y, __ldg(wp + (k2+1)*F2), a);
        }
        f2s[i] = a;
    }
    __syncthreads();
    for (int i = t; i < NH2*NN; i += NT) {
        int h = i / NN, n = i - h*NN;
        const float* fr = f2s + n*9 + h*3;
        float a = fr[0]*__ldg(as2+h*3) + fr[1]*__ldg(as2+h*3+1) + fr[2]*__ldg(as2+h*3+2);
        float c = fr[0]*__ldg(an2+h*3) + fr[1]*__ldg(an2+h*3+1) + fr[2]*__ldg(an2+h*3+2);
        es2[i] = a; en2[i] = c;
    }
    __syncthreads();

    // ---- layer-2 softmax + aggregate (warp per (h,row)) -------------------
    for (int task = w; task < NH2*NN; task += 16) {
        int h = task / NN, n = task - h*NN;
        float esr = es2[task];
        float ev[4]; unsigned bits[4];
        float m = -1e30f;
        #pragma unroll
        for (int q = 0; q < 4; q++) {
            int j = q*32 + lane;
            unsigned bit = 0; float e = -1e30f;
            if (j < NN) {
                bit = (Amask[n*4 + q] >> lane) & 1u;
                e = esr + en2[h*NN + j];
                e = fmaxf(e, ALPHA*e);
                if (bit) m = fmaxf(m, e);
            }
            ev[q] = e; bits[q] = bit;
        }
        m = wred_max(m);
        float s0 = 0.f, s1 = 0.f, s2 = 0.f, s3 = 0.f;
        #pragma unroll
        for (int q = 0; q < 4; q++) {
            int j = q*32 + lane;
            if (j < NN && bits[q]) {
                float p = __expf(ev[q] - m);
                const float* fj = f2s + j*9 + h*3;
                s0 += p;
                s1 = fmaf(p, fj[0], s1);
                s2 = fmaf(p, fj[1], s2);
                s3 = fmaf(p, fj[2], s3);
            }
        }
        s0 = wred_sum(s0); s1 = wred_sum(s1); s2 = wred_sum(s2); s3 = wred_sum(s3);
        if (lane == 0) {
            float inv = 1.f / s0;
            ho2[n*9 + h*3 + 0] = s1*inv;
            ho2[n*9 + h*3 + 1] = s2*inv;
            ho2[n*9 + h*3 + 2] = s3*inv;
        }
    }
    __syncthreads();

    // ---- head mean + lrelu + fc1 + sigmoid --------------------------------
    if (t < NN) {
        int n = t;
        float s = 0.f;
        #pragma unroll
        for (int f = 0; f < 3; f++) {
            float v = (ho2[n*9 + f] + ho2[n*9 + 3 + f] + ho2[n*9 + 6 + f]) * (1.f/3.f)
                      + __ldg(b2 + f);
            v = fmaxf(v, ALPHA*v);
            s = fmaf(v, __ldg(fc1 + f), s);
        }
        ts[n] = 1.f/(1.f + __expf(-s));
    }
    __syncthreads();

    // ---- y = t @ fc2 -------------------------------------------------------
    if (t < NN) {
        int j = t;
        float a = 0.f;
        #pragma unroll 2
        for (int n = 0; n < NN; n++) a = fmaf(ts[n], __ldg(fc2 + n*NN + j), a);
        ys[j] = a;
    }
    __syncthreads();

    // ---- final: out[b] = sum_j t[j]*softmax(y)[j] --------------------------
    if (t < 32) {
        float yv[4];
        float m = -1e30f;
        #pragma unroll
        for (int q = 0; q < 4; q++) {
            int j = q*32 + t;
            yv[q] = (j < NN) ? ys[j] : -1e30f;
            m = fmaxf(m, yv[q]);
        }
        m = wred_max(m);
        float S = 0.f, T = 0.f;
        #pragma unroll
        for (int q = 0; q < 4; q++) {
            int j = q*32 + t;
            if (j < NN) {
                float p = __expf(yv[q] - m);
                S += p;
                T = fmaf(ts[j], p, T);
            }
        }
        S = wred_sum(S); T = wred_sum(T);
        if (t == 0) out[b] = T / S;
    }
}

extern "C" void kernel_launch(void* const* d_in, const int* in_sizes, int n_in,
                              void* d_out, int out_size) {
    (void)in_sizes; (void)n_in; (void)out_size;
    const float* X   = (const float*)d_in[0];
    const float* A   = (const float*)d_in[1];
    const float* M   = (const float*)d_in[2];
    const float* W1  = (const float*)d_in[3];
    const float* as1 = (const float*)d_in[4];
    const float* an1 = (const float*)d_in[5];
    const float* b1  = (const float*)d_in[6];
    const float* W2  = (const float*)d_in[7];
    const float* as2 = (const float*)d_in[8];
    const float* an2 = (const float*)d_in[9];
    const float* b2  = (const float*)d_in[10];
    const float* fc1 = (const float*)d_in[11];
    const float* fc2 = (const float*)d_in[12];

    cudaFuncSetAttribute(gat_kernel, cudaFuncAttributeMaxDynamicSharedMemorySize, SMEM_BYTES);

    prep_kernel<<<(NN*HF1 + 255)/256, 256>>>(M, W1);
    gat_kernel<<<BB, NT, SMEM_BYTES>>>(X, A, as1, an1, b1,
                                       W2, as2, an2, b2, fc1, fc2,
                                       (float*)d_out);
}